// round 14
// baseline (speedup 1.0000x reference)
#include <cuda_runtime.h>
#include <cuda_fp16.h>
#include <cstdint>

#define N_NODES 50000
#define EMBED_DIM 512
#define N_EDGES 800000
#define NEG_SLOPE 0.01f

#define SCAN_BLOCKS 196   // ceil(50000/256)

// -------- scratch (allocation-free: __device__ globals) --------
__device__ uint32_t g_Hs_h[(size_t)N_NODES * (EMBED_DIM / 2)];  // fp16x2 packed H (unscaled)
__device__ uint32_t g_Xh[(size_t)N_NODES * (EMBED_DIM / 2)];    // fp16x2 packed X
__device__ __half   g_Wh_t[EMBED_DIM * EMBED_DIM];              // W^T as fp16: [n][k]
__device__ int   g_deg[N_NODES];
__device__ float g_dinv[N_NODES];
__device__ int   g_row_start[N_NODES + 1];
__device__ int   g_cursor[N_NODES];
__device__ int   g_csr_src[N_EDGES];
__device__ int   g_blk[SCAN_BLOCKS];
__device__ int   g_blk_pref[SCAN_BLOCKS];

// -------------------- converts --------------------
__global__ __launch_bounds__(256) void convert_x_kernel(const float* __restrict__ X) {
    size_t i = (size_t)blockIdx.x * blockDim.x + threadIdx.x;  // 8 floats per thread
    const size_t total = (size_t)N_NODES * EMBED_DIM / 8;
    if (i >= total) return;
    const float4* x4 = reinterpret_cast<const float4*>(X);
    float4 f0 = __ldg(&x4[2 * i]);
    float4 f1 = __ldg(&x4[2 * i + 1]);
    uint4 o;
    __half2 h;
    h = __floats2half2_rn(f0.x, f0.y); o.x = *reinterpret_cast<uint32_t*>(&h);
    h = __floats2half2_rn(f0.z, f0.w); o.y = *reinterpret_cast<uint32_t*>(&h);
    h = __floats2half2_rn(f1.x, f1.y); o.z = *reinterpret_cast<uint32_t*>(&h);
    h = __floats2half2_rn(f1.z, f1.w); o.w = *reinterpret_cast<uint32_t*>(&h);
    reinterpret_cast<uint4*>(g_Xh)[i] = o;
}

// W[k][n] -> g_Wh_t[n][k] fp16
__global__ void convert_w_kernel(const float* __restrict__ W) {
    __shared__ float t[32][33];
    int bx = blockIdx.x * 32, by = blockIdx.y * 32;
    int tx = threadIdx.x, ty = threadIdx.y;
    #pragma unroll
    for (int i = 0; i < 32; i += 8)
        t[ty + i][tx] = W[(size_t)(by + ty + i) * EMBED_DIM + bx + tx];
    __syncthreads();
    #pragma unroll
    for (int i = 0; i < 32; i += 8)
        g_Wh_t[(size_t)(bx + ty + i) * EMBED_DIM + by + tx] = __float2half_rn(t[tx][ty + i]);
}

// -------------------- degree --------------------
__global__ void init_deg_kernel() {
    int i = blockIdx.x * blockDim.x + threadIdx.x;
    if (i < N_NODES) g_deg[i] = 1;  // self-loop
}
__global__ void count_deg_kernel(const int* __restrict__ dst) {
    int e = blockIdx.x * blockDim.x + threadIdx.x;
    if (e < N_EDGES) atomicAdd(&g_deg[dst[e]], 1);
}

// -------------------- 3-pass scan of (deg-1) --------------------
__global__ __launch_bounds__(256) void scan_passA() {
    __shared__ int wsum[8];
    int i = blockIdx.x * 256 + threadIdx.x;
    int v = (i < N_NODES) ? (g_deg[i] - 1) : 0;
    #pragma unroll
    for (int o = 16; o > 0; o >>= 1) v += __shfl_down_sync(0xffffffff, v, o);
    if ((threadIdx.x & 31) == 0) wsum[threadIdx.x >> 5] = v;
    __syncthreads();
    if (threadIdx.x < 8) {
        int s = wsum[threadIdx.x];
        #pragma unroll
        for (int o = 4; o > 0; o >>= 1) s += __shfl_down_sync(0xff, s, o);
        if (threadIdx.x == 0) g_blk[blockIdx.x] = s;
    }
}
__global__ __launch_bounds__(256) void scan_passB() {
    __shared__ int wsum[8];
    int t = threadIdx.x;
    int v = (t < SCAN_BLOCKS) ? g_blk[t] : 0;
    int lane = t & 31, w = t >> 5;
    int inc = v;
    #pragma unroll
    for (int o = 1; o < 32; o <<= 1) {
        int u = __shfl_up_sync(0xffffffff, inc, o);
        if (lane >= o) inc += u;
    }
    if (lane == 31) wsum[w] = inc;
    __syncthreads();
    if (t < 8) {
        int s = wsum[t];
        int si = s;
        #pragma unroll
        for (int o = 1; o < 8; o <<= 1) {
            int u = __shfl_up_sync(0xff, si, o);
            if (t >= o) si += u;
        }
        wsum[t] = si - s;
    }
    __syncthreads();
    if (t < SCAN_BLOCKS) g_blk_pref[t] = wsum[w] + inc - v;
}
__global__ __launch_bounds__(256) void scan_passC() {
    __shared__ int wsum[8];
    int i = blockIdx.x * 256 + threadIdx.x;
    int deg = (i < N_NODES) ? g_deg[i] : 1;
    int v = deg - 1;
    int lane = threadIdx.x & 31, w = threadIdx.x >> 5;
    int inc = v;
    #pragma unroll
    for (int o = 1; o < 32; o <<= 1) {
        int u = __shfl_up_sync(0xffffffff, inc, o);
        if (lane >= o) inc += u;
    }
    if (lane == 31) wsum[w] = inc;
    __syncthreads();
    if (threadIdx.x < 8) {
        int s = wsum[threadIdx.x];
        int si = s;
        #pragma unroll
        for (int o = 1; o < 8; o <<= 1) {
            int u = __shfl_up_sync(0xff, si, o);
            if (threadIdx.x >= o) si += u;
        }
        wsum[threadIdx.x] = si - s;
    }
    __syncthreads();
    if (i < N_NODES) {
        int ex = g_blk_pref[blockIdx.x] + wsum[w] + inc - v;
        g_row_start[i] = ex;
        g_cursor[i] = ex;
        g_dinv[i] = rsqrtf((float)deg);
    }
    if (i == 0) g_row_start[N_NODES] = N_EDGES;
}

__global__ void csr_fill_kernel(const int* __restrict__ src, const int* __restrict__ dst) {
    int e = blockIdx.x * blockDim.x + threadIdx.x;
    if (e >= N_EDGES) return;
    int d = dst[e];
    int pos = atomicAdd(&g_cursor[d], 1);
    g_csr_src[pos] = src[e];
}

// ==================== fp16 mma.sync GEMM (m16n8k16) ====================
#define BM 128
#define BN 128
#define BK 64
#define T_ROW_STRIDE 144
#define A_TILE_BYTES (BM * T_ROW_STRIDE)
#define B_TILE_BYTES (BN * T_ROW_STRIDE)
#define STAGE_BYTES (A_TILE_BYTES + B_TILE_BYTES)
#define SMEM_TOTAL (2 * STAGE_BYTES)

__device__ __forceinline__ uint32_t smem_u32(const void* p) {
    uint32_t a;
    asm("{ .reg .u64 t; cvta.to.shared.u64 t, %1; cvt.u32.u64 %0, t; }" : "=r"(a) : "l"(p));
    return a;
}
__device__ __forceinline__ void cp_async16(uint32_t dst, const void* src, int sz) {
    asm volatile("cp.async.cg.shared.global [%0], [%1], 16, %2;"
                 :: "r"(dst), "l"(src), "r"(sz));
}
__device__ __forceinline__ void mma_f16(float& d0, float& d1, float& d2, float& d3,
                                        uint32_t a0, uint32_t a1, uint32_t a2, uint32_t a3,
                                        uint32_t b0, uint32_t b1) {
    asm volatile(
        "mma.sync.aligned.m16n8k16.row.col.f32.f16.f16.f32 "
        "{%0,%1,%2,%3}, {%4,%5,%6,%7}, {%8,%9}, {%0,%1,%2,%3};"
        : "+f"(d0), "+f"(d1), "+f"(d2), "+f"(d3)
        : "r"(a0), "r"(a1), "r"(a2), "r"(a3), "r"(b0), "r"(b1));
}

__device__ __forceinline__ void load_chunk(int rowBase, int colBase, int k0,
                                           uint32_t sA, uint32_t sB, int tid) {
    const __half* Xh = reinterpret_cast<const __half*>(g_Xh);
    #pragma unroll
    for (int s = 0; s < 4; s++) {
        int q = tid + s * 256;
        int r = q >> 3, ch = q & 7;
        int gRow = rowBase + r;
        int ok = (gRow < N_NODES);
        const __half* src = Xh + (size_t)(ok ? gRow : 0) * EMBED_DIM + k0 + ch * 8;
        cp_async16(sA + r * T_ROW_STRIDE + ch * 16, src, ok ? 16 : 0);
    }
    #pragma unroll
    for (int s = 0; s < 4; s++) {
        int q = tid + s * 256;
        int n = q >> 3, ch = q & 7;
        const __half* src = g_Wh_t + (size_t)(colBase + n) * EMBED_DIM + k0 + ch * 8;
        cp_async16(sB + n * T_ROW_STRIDE + ch * 16, src, 16);
    }
}

__global__ __launch_bounds__(256, 2) void gemm_mma_kernel(int colOffset)
{
    extern __shared__ char smem[];
    const uint32_t sbase = smem_u32(smem);
    const int tid = threadIdx.x;
    const int rowBase = blockIdx.y * BM;
    const int colBase = blockIdx.x * BN + colOffset;

    const int w = tid >> 5, lane = tid & 31;
    const int warpM = w & 1, warpN = w >> 1;
    const int g = lane >> 2, c4 = lane & 3;

    float acc[4][4][4];
    #pragma unroll
    for (int i = 0; i < 4; i++)
        #pragma unroll
        for (int j = 0; j < 4; j++)
            #pragma unroll
            for (int r = 0; r < 4; r++) acc[i][j][r] = 0.f;

    load_chunk(rowBase, colBase, 0, sbase, sbase + A_TILE_BYTES, tid);
    asm volatile("cp.async.commit_group;" ::: "memory");
    load_chunk(rowBase, colBase, BK,
               sbase + STAGE_BYTES, sbase + STAGE_BYTES + A_TILE_BYTES, tid);
    asm volatile("cp.async.commit_group;" ::: "memory");

    const int NCHUNKS = EMBED_DIM / BK;  // 8
    for (int cidx = 0; cidx < NCHUNKS; cidx++) {
        const int buf = cidx & 1;
        asm volatile("cp.async.wait_group 1;" ::: "memory");
        __syncthreads();

        const char* As = smem + buf * STAGE_BYTES;
        const char* Bs = As + A_TILE_BYTES;
        const int aRow0 = warpM * 64 + g;
        const int bCol0 = warpN * 32 + g;

        #pragma unroll
        for (int ks = 0; ks < 4; ks++) {
            const int k0 = ks * 16;
            uint32_t af[4][4], bf[4][2];
            #pragma unroll
            for (int i = 0; i < 4; i++) {
                const char* base = As + (aRow0 + i * 16) * T_ROW_STRIDE + (k0 + 2 * c4) * 2;
                af[i][0] = *(const uint32_t*)(base);
                af[i][1] = *(const uint32_t*)(base + 8 * T_ROW_STRIDE);
                af[i][2] = *(const uint32_t*)(base + 16);
                af[i][3] = *(const uint32_t*)(base + 8 * T_ROW_STRIDE + 16);
            }
            #pragma unroll
            for (int j = 0; j < 4; j++) {
                const char* base = Bs + (bCol0 + j * 8) * T_ROW_STRIDE + (k0 + 2 * c4) * 2;
                bf[j][0] = *(const uint32_t*)(base);
                bf[j][1] = *(const uint32_t*)(base + 16);
            }
            #pragma unroll
            for (int i = 0; i < 4; i++)
                #pragma unroll
                for (int j = 0; j < 4; j++)
                    mma_f16(acc[i][j][0], acc[i][j][1], acc[i][j][2], acc[i][j][3],
                            af[i][0], af[i][1], af[i][2], af[i][3],
                            bf[j][0], bf[j][1]);
        }

        __syncthreads();
        if (cidx + 2 < NCHUNKS) {
            load_chunk(rowBase, colBase, (cidx + 2) * BK,
                       sbase + buf * STAGE_BYTES,
                       sbase + buf * STAGE_BYTES + A_TILE_BYTES, tid);
        }
        asm volatile("cp.async.commit_group;" ::: "memory");
    }

    // epilogue: pack raw H to fp16x2 (no dinv — applied in gather)
    const int hbase = (colBase + warpN * 32) / 2 + c4;
    #pragma unroll
    for (int i = 0; i < 4; i++) {
        #pragma unroll
        for (int half = 0; half < 2; half++) {
            int row = rowBase + warpM * 64 + i * 16 + g + half * 8;
            if (row >= N_NODES) continue;
            size_t base = (size_t)row * (EMBED_DIM / 2) + hbase;
            #pragma unroll
            for (int j = 0; j < 4; j++) {
                __half2 h = __floats2half2_rn(acc[i][j][half * 2 + 0],
                                              acc[i][j][half * 2 + 1]);
                g_Hs_h[base + j * 4] = *reinterpret_cast<uint32_t*>(&h);
            }
        }
    }
}

// ---- gather (column half): out[n, half] = leaky(dinv[n]*sum + b) ----
__device__ __forceinline__ void acc8s(float* a, uint4 v, float s) {
    float2 f;
    f = __half22float2(*reinterpret_cast<__half2*>(&v.x)); a[0] = fmaf(f.x, s, a[0]); a[1] = fmaf(f.y, s, a[1]);
    f = __half22float2(*reinterpret_cast<__half2*>(&v.y)); a[2] = fmaf(f.x, s, a[2]); a[3] = fmaf(f.y, s, a[3]);
    f = __half22float2(*reinterpret_cast<__half2*>(&v.z)); a[4] = fmaf(f.x, s, a[4]); a[5] = fmaf(f.y, s, a[5]);
    f = __half22float2(*reinterpret_cast<__half2*>(&v.w)); a[6] = fmaf(f.x, s, a[6]); a[7] = fmaf(f.y, s, a[7]);
}

__global__ __launch_bounds__(256) void gather_half_kernel(
    const float* __restrict__ b, float* __restrict__ out, int halfIdx)
{
    int node = (blockIdx.x * blockDim.x + threadIdx.x) >> 5;
    if (node >= N_NODES) return;
    int lane = threadIdx.x & 31;
    const int h32 = halfIdx * 32;  // uint4 offset within row

    const uint4* hs = reinterpret_cast<const uint4*>(g_Hs_h);  // 64 uint4 per row
    const float sc = g_dinv[node];

    float acc[8];
    #pragma unroll
    for (int i = 0; i < 8; i++) acc[i] = 0.f;
    {   // self-loop term
        uint4 v0 = __ldg(&hs[(size_t)node * 64 + h32 + lane]);
        acc8s(acc, v0, sc);
    }

    int e = g_row_start[node];
    const int end = g_row_start[node + 1];

    // unroll x4 for MLP (4 outstanding 16B row loads)
    for (; e + 4 <= end; e += 4) {
        int s0 = __ldg(&g_csr_src[e]);
        int s1 = __ldg(&g_csr_src[e + 1]);
        int s2 = __ldg(&g_csr_src[e + 2]);
        int s3 = __ldg(&g_csr_src[e + 3]);
        float d0 = __ldg(&g_dinv[s0]);
        float d1 = __ldg(&g_dinv[s1]);
        float d2 = __ldg(&g_dinv[s2]);
        float d3 = __ldg(&g_dinv[s3]);
        uint4 a0 = __ldg(&hs[(size_t)s0 * 64 + h32 + lane]);
        uint4 a1 = __ldg(&hs[(size_t)s1 * 64 + h32 + lane]);
        uint4 a2 = __ldg(&hs[(size_t)s2 * 64 + h32 + lane]);
        uint4 a3 = __ldg(&hs[(size_t)s3 * 64 + h32 + lane]);
        acc8s(acc, a0, d0);
        acc8s(acc, a1, d1);
        acc8s(acc, a2, d2);
        acc8s(acc, a3, d3);
    }
    for (; e < end; e++) {
        int s0 = __ldg(&g_csr_src[e]);
        float d0 = __ldg(&g_dinv[s0]);
        uint4 a0 = __ldg(&hs[(size_t)s0 * 64 + h32 + lane]);
        acc8s(acc, a0, d0);
    }

    const float4* b4 = reinterpret_cast<const float4*>(b);
    float4* o4 = reinterpret_cast<float4*>(&out[(size_t)node * EMBED_DIM]);
    const int u = h32 + lane;  // uint4 column index (0..63)
    #pragma unroll
    for (int q = 0; q < 2; q++) {
        float4 bb = __ldg(&b4[u * 2 + q]);
        float4 v;
        float t;
        t = acc[q * 4 + 0] * sc + bb.x; v.x = (t >= 0.f) ? t : NEG_SLOPE * t;
        t = acc[q * 4 + 1] * sc + bb.y; v.y = (t >= 0.f) ? t : NEG_SLOPE * t;
        t = acc[q * 4 + 2] * sc + bb.z; v.z = (t >= 0.f) ? t : NEG_SLOPE * t;
        t = acc[q * 4 + 3] * sc + bb.w; v.w = (t >= 0.f) ? t : NEG_SLOPE * t;
        o4[u * 2 + q] = v;
    }
}

// -------------------- launch --------------------
extern "C" void kernel_launch(void* const* d_in, const int* in_sizes, int n_in,
                              void* d_out, int out_size) {
    const float* X = (const float*)d_in[0];
    const float* W = (const float*)d_in[1];
    const float* b = (const float*)d_in[2];
    const int* edge = (const int*)d_in[3];
    const int* src = edge;
    const int* dst = edge + N_EDGES;
    float* out = (float*)d_out;

    // one-time host-side resources (no device memory involved)
    static cudaStream_t s1 = nullptr, s2 = nullptr;
    static cudaEvent_t evFork = nullptr, evCsr = nullptr, evG1 = nullptr, evJ2 = nullptr;
    if (s1 == nullptr) {
        cudaStreamCreateWithFlags(&s1, cudaStreamNonBlocking);
        cudaStreamCreateWithFlags(&s2, cudaStreamNonBlocking);
        cudaEventCreateWithFlags(&evFork, cudaEventDisableTiming);
        cudaEventCreateWithFlags(&evCsr, cudaEventDisableTiming);
        cudaEventCreateWithFlags(&evG1, cudaEventDisableTiming);
        cudaEventCreateWithFlags(&evJ2, cudaEventDisableTiming);
    }

    // fork both side streams from the origin stream
    cudaEventRecord(evFork, 0);
    cudaStreamWaitEvent(s1, evFork, 0);
    cudaStreamWaitEvent(s2, evFork, 0);

    // s1: degree + CSR chain
    init_deg_kernel<<<(N_NODES + 255) / 256, 256, 0, s1>>>();
    count_deg_kernel<<<(N_EDGES + 255) / 256, 256, 0, s1>>>(dst);
    scan_passA<<<SCAN_BLOCKS, 256, 0, s1>>>();
    scan_passB<<<1, 256, 0, s1>>>();
    scan_passC<<<SCAN_BLOCKS, 256, 0, s1>>>();
    csr_fill_kernel<<<(N_EDGES + 255) / 256, 256, 0, s1>>>(src, dst);
    cudaEventRecord(evCsr, s1);

    // main: converts + GEMM half 1 (cols 0..255)
    size_t cx_threads = (size_t)N_NODES * EMBED_DIM / 8;
    convert_x_kernel<<<(unsigned)((cx_threads + 255) / 256), 256>>>(X);
    convert_w_kernel<<<dim3(16, 16), dim3(32, 8)>>>(W);

    cudaFuncSetAttribute(gemm_mma_kernel,
                         cudaFuncAttributeMaxDynamicSharedMemorySize, SMEM_TOTAL);
    dim3 ggrid(2, (N_NODES + BM - 1) / BM);   // 2 col-tiles per half
    gemm_mma_kernel<<<ggrid, 256, SMEM_TOTAL>>>(0);
    cudaEventRecord(evG1, 0);

    // main: GEMM half 2 (cols 256..511)
    gemm_mma_kernel<<<ggrid, 256, SMEM_TOTAL>>>(256);

    // s2: gather half 1 overlapped with GEMM half 2
    cudaStreamWaitEvent(s2, evG1, 0);
    cudaStreamWaitEvent(s2, evCsr, 0);
    gather_half_kernel<<<(N_NODES + 7) / 8, 256, 0, s2>>>(b, out, 0);
    cudaEventRecord(evJ2, s2);

    // main: gather half 2, then join s2
    cudaStreamWaitEvent(0, evCsr, 0);
    gather_half_kernel<<<(N_NODES + 7) / 8, 256>>>(b, out, 1);
    cudaStreamWaitEvent(0, evJ2, 0);
}